// round 1
// baseline (speedup 1.0000x reference)
#include <cuda_runtime.h>

#define N_BANDS   224
#define DM        64
#define DS        16
#define N_TILE    4
#define NTHREADS  256
#define LN_EPS    1e-5f

__global__ __launch_bounds__(NTHREADS) void spectral_ssm_kernel(
    const float* __restrict__ x,      // (N, 224)
    const float* __restrict__ w_in,   // (64,)
    const float* __restrict__ b_in,   // (64,)
    const float* __restrict__ A_log,  // (64,16)
    const float* __restrict__ Wb,     // (64,16)
    const float* __restrict__ Wc,     // (64,16)
    const float* __restrict__ Dvec,   // (64,)
    const float* __restrict__ Wo,     // (64,64) torch (out,in)
    const float* __restrict__ bo,     // (64,)
    const float* __restrict__ gamma,  // (64,)
    const float* __restrict__ beta,   // (64,)
    float* __restrict__ out)          // (N, 64)
{
    __shared__ float sh_x[N_TILE][N_BANDS];
    __shared__ float sh_wb[DS], sh_bb[DS], sh_wc[DS], sh_bc[DS];
    __shared__ float sh_WoT[DM][DM + 1];   // padded: WoT[k][d] = Wo[d][k]
    __shared__ float sh_out[N_TILE][DM];
    __shared__ float sh_z[N_TILE][DM];

    const int tid = threadIdx.x;
    const int d   = tid & (DM - 1);
    const int nl  = tid >> 6;
    const int n0  = blockIdx.x * N_TILE;

    // ---- load x tile (coalesced) ----
    #pragma unroll
    for (int i = tid; i < N_TILE * N_BANDS; i += NTHREADS) {
        int nn = i / N_BANDS, cc = i - nn * N_BANDS;
        sh_x[nn][cc] = x[(size_t)(n0 + nn) * N_BANDS + cc];
    }
    // ---- load Wo transposed into padded smem ----
    #pragma unroll
    for (int i = tid; i < DM * DM; i += NTHREADS) {
        int r = i >> 6, k = i & (DM - 1);     // Wo[r][k]
        sh_WoT[k][r] = Wo[i];
    }
    // ---- tiny projections: wb = w_in^T Wb, bb = b_in^T Wb, same for Wc ----
    if (tid < 64) {
        int s = tid & (DS - 1);
        int which = tid >> 4;
        float acc = 0.f;
        const float* W = (which < 2) ? Wb : Wc;
        const float* v = (which & 1) ? b_in : w_in;
        #pragma unroll 16
        for (int dd = 0; dd < DM; ++dd) acc += v[dd] * W[dd * DS + s];
        if (which == 0)      sh_wb[s] = acc;
        else if (which == 1) sh_bb[s] = acc;
        else if (which == 2) sh_wc[s] = acc;
        else                 sh_bc[s] = acc;
    }
    __syncthreads();

    // ---- per-thread decay values a[d][s] = exp(-exp(A_log)) ----
    float a[DS];
    #pragma unroll
    for (int s = 0; s < DS; ++s)
        a[s] = expf(-expf(A_log[d * DS + s]));

    // ---- pack decays + zero accumulators (f32x2 lanes: (2i, 2i+1)) ----
    unsigned long long ap[DS / 2], s1p[DS / 2], s2p[DS / 2];
    #pragma unroll
    for (int i = 0; i < DS / 2; ++i) {
        asm("mov.b64 %0, {%1, %2};" : "=l"(ap[i]) : "f"(a[2 * i]), "f"(a[2 * i + 1]));
        s1p[i] = 0ULL;
        s2p[i] = 0ULL;
    }

    // ---- main Horner loop over bands: S1 = S1*a + x ; S2 = S2*a + x^2 ----
    const float* xr = sh_x[nl];
    #pragma unroll 4
    for (int c = 0; c < N_BANDS; ++c) {
        float xv = xr[c];
        float xx = xv * xv;
        unsigned long long xp, xxp;
        asm("mov.b64 %0, {%1, %1};" : "=l"(xp)  : "f"(xv));
        asm("mov.b64 %0, {%1, %1};" : "=l"(xxp) : "f"(xx));
        #pragma unroll
        for (int i = 0; i < DS / 2; ++i) {
            asm("fma.rn.f32x2 %0, %1, %2, %3;"
                : "=l"(s1p[i]) : "l"(s1p[i]), "l"(ap[i]), "l"(xp));
            asm("fma.rn.f32x2 %0, %1, %2, %3;"
                : "=l"(s2p[i]) : "l"(s2p[i]), "l"(ap[i]), "l"(xxp));
        }
    }

    // ---- unpack ----
    float S1[DS], S2[DS];
    #pragma unroll
    for (int i = 0; i < DS / 2; ++i) {
        asm("mov.b64 {%0, %1}, %2;" : "=f"(S1[2 * i]), "=f"(S1[2 * i + 1]) : "l"(s1p[i]));
        asm("mov.b64 {%0, %1}, %2;" : "=f"(S2[2 * i]), "=f"(S2[2 * i + 1]) : "l"(s2p[i]));
    }

    // ---- epilogue: y[n,d] = sum_s h_final * C_last ----
    const float wd = w_in[d];
    const float bd = b_in[d];
    const float xlast = xr[N_BANDS - 1];
    float y = 0.f;
    #pragma unroll
    for (int s = 0; s < DS; ++s) {
        float av = a[s];
        // geometric: S0 = sum_{j=0}^{223} a^j
        float S0 = (1.0f - __powf(av, (float)N_BANDS)) / (1.0f - av);
        float wbv = sh_wb[s], bbv = sh_bb[s];
        float hf = wd * wbv * S2[s] + (wd * bbv + bd * wbv) * S1[s] + bd * bbv * S0;
        float cl = xlast * sh_wc[s] + sh_bc[s];
        y += hf * cl;
    }
    float o = y + Dvec[d] * (xlast * wd + bd);
    sh_out[nl][d] = o;
    __syncthreads();

    // ---- z = out @ Wo^T + bo ----
    float z = bo[d];
    #pragma unroll 16
    for (int k = 0; k < DM; ++k)
        z += sh_out[nl][k] * sh_WoT[k][d];
    sh_z[nl][d] = z;
    __syncthreads();

    // ---- layernorm over d ----
    float mu = 0.f;
    #pragma unroll 16
    for (int k = 0; k < DM; ++k) mu += sh_z[nl][k];
    mu *= (1.0f / DM);
    float m2 = 0.f;
    #pragma unroll 16
    for (int k = 0; k < DM; ++k) {
        float v = sh_z[nl][k] - mu;
        m2 += v * v;
    }
    m2 *= (1.0f / DM);
    float r = rsqrtf(m2 + LN_EPS);

    out[(size_t)(n0 + nl) * DM + d] = gamma[d] * (z - mu) * r + beta[d];
}

extern "C" void kernel_launch(void* const* d_in, const int* in_sizes, int n_in,
                              void* d_out, int out_size) {
    const float* x     = (const float*)d_in[0];
    const float* w_in  = (const float*)d_in[1];
    const float* b_in  = (const float*)d_in[2];
    const float* A_log = (const float*)d_in[3];
    const float* Wb    = (const float*)d_in[4];
    const float* Wc    = (const float*)d_in[5];
    const float* Dv    = (const float*)d_in[6];
    const float* Wo    = (const float*)d_in[7];
    const float* bo    = (const float*)d_in[8];
    const float* gm    = (const float*)d_in[9];
    const float* bt    = (const float*)d_in[10];
    float* out = (float*)d_out;

    int N = in_sizes[0] / N_BANDS;          // 4096
    int grid = N / N_TILE;                  // 1024 blocks
    spectral_ssm_kernel<<<grid, NTHREADS>>>(x, w_in, b_in, A_log, Wb, Wc, Dv,
                                            Wo, bo, gm, bt, out);
}

// round 2
// speedup vs baseline: 2.2252x; 2.2252x over previous
#include <cuda_runtime.h>

#define N_BANDS   224
#define DM        64
#define DS        16
#define N_TILE    4
#define NTHREADS  256
#define LN_EPS    1e-5f

__global__ __launch_bounds__(NTHREADS) void spectral_ssm_kernel(
    const float* __restrict__ x,      // (N, 224)
    const float* __restrict__ w_in,   // (64,)
    const float* __restrict__ b_in,   // (64,)
    const float* __restrict__ A_log,  // (64,16)
    const float* __restrict__ Wb,     // (64,16)
    const float* __restrict__ Wc,     // (64,16)
    const float* __restrict__ Dvec,   // (64,)
    const float* __restrict__ Wo,     // (64,64) torch (out,in)
    const float* __restrict__ bo,     // (64,)
    const float* __restrict__ gamma,  // (64,)
    const float* __restrict__ beta,   // (64,)
    float* __restrict__ out)          // (N, 64)
{
    __shared__ float sh_x[N_TILE][N_BANDS];
    __shared__ float sh_wb[DS], sh_bb[DS], sh_wc[DS], sh_bc[DS];
    __shared__ float sh_WoT[DM][DM + 1];   // padded: WoT[k][d] = Wo[d][k]
    __shared__ float sh_out[N_TILE][DM];
    __shared__ float sh_z[N_TILE][DM];

    const int tid = threadIdx.x;
    const int d   = tid & (DM - 1);
    const int nl  = tid >> 6;
    const int n0  = blockIdx.x * N_TILE;

    // ---- load x tile (coalesced) ----
    #pragma unroll
    for (int i = tid; i < N_TILE * N_BANDS; i += NTHREADS) {
        int nn = i / N_BANDS, cc = i - nn * N_BANDS;
        sh_x[nn][cc] = x[(size_t)(n0 + nn) * N_BANDS + cc];
    }
    // ---- load Wo transposed into padded smem ----
    #pragma unroll
    for (int i = tid; i < DM * DM; i += NTHREADS) {
        int r = i >> 6, k = i & (DM - 1);     // Wo[r][k]
        sh_WoT[k][r] = Wo[i];
    }
    // ---- tiny projections: wb = w_in^T Wb, bb = b_in^T Wb, same for Wc ----
    if (tid < 64) {
        int s = tid & (DS - 1);
        int which = tid >> 4;
        float acc = 0.f;
        const float* W = (which < 2) ? Wb : Wc;
        const float* v = (which & 1) ? b_in : w_in;
        #pragma unroll 16
        for (int dd = 0; dd < DM; ++dd) acc += v[dd] * W[dd * DS + s];
        if (which == 0)      sh_wb[s] = acc;
        else if (which == 1) sh_bb[s] = acc;
        else if (which == 2) sh_wc[s] = acc;
        else                 sh_bc[s] = acc;
    }
    __syncthreads();

    // ---- per-thread decay values a[d][s] = exp(-exp(A_log)) ----
    // Track e_min = min_s exp(A_log) -> a_max = exp(-e_min). Bands older than
    // K = ceil(34 / e_min) contribute relatively <= a_max^K <= exp(-34) ~ 1.7e-15:
    // below fp32 resolution. Runtime-computed, so this is exact for any data
    // (a -> 1 would simply give K >= 224 = full loop).
    float a[DS];
    float e_min = 1e30f;
    #pragma unroll
    for (int s = 0; s < DS; ++s) {
        float e = expf(A_log[d * DS + s]);
        e_min = fminf(e_min, e);
        a[s] = expf(-e);
    }
    int K = (int)ceilf(34.0f / e_min);
    K = min(K, N_BANDS);
    // warp-uniform start (extra iterations for low-K lanes only add accuracy)
    unsigned Kw = __reduce_max_sync(0xffffffffu, (unsigned)K);
    const int c0 = N_BANDS - (int)Kw;

    // ---- pack decays + zero accumulators (f32x2 lanes: (2i, 2i+1)) ----
    unsigned long long ap[DS / 2], s1p[DS / 2], s2p[DS / 2];
    #pragma unroll
    for (int i = 0; i < DS / 2; ++i) {
        asm("mov.b64 %0, {%1, %2};" : "=l"(ap[i]) : "f"(a[2 * i]), "f"(a[2 * i + 1]));
        s1p[i] = 0ULL;
        s2p[i] = 0ULL;
    }

    // ---- truncated Horner loop: S1 = S1*a + x ; S2 = S2*a + x^2 ----
    const float* xr = sh_x[nl];
    #pragma unroll 4
    for (int c = c0; c < N_BANDS; ++c) {
        float xv = xr[c];
        unsigned long long xp, xxp;
        asm("mov.b64 %0, {%1, %1};" : "=l"(xp) : "f"(xv));
        asm("mul.rn.f32x2 %0, %1, %2;" : "=l"(xxp) : "l"(xp), "l"(xp));
        #pragma unroll
        for (int i = 0; i < DS / 2; ++i) {
            asm("fma.rn.f32x2 %0, %1, %2, %3;"
                : "=l"(s1p[i]) : "l"(s1p[i]), "l"(ap[i]), "l"(xp));
            asm("fma.rn.f32x2 %0, %1, %2, %3;"
                : "=l"(s2p[i]) : "l"(s2p[i]), "l"(ap[i]), "l"(xxp));
        }
    }

    // ---- unpack ----
    float S1[DS], S2[DS];
    #pragma unroll
    for (int i = 0; i < DS / 2; ++i) {
        asm("mov.b64 {%0, %1}, %2;" : "=f"(S1[2 * i]), "=f"(S1[2 * i + 1]) : "l"(s1p[i]));
        asm("mov.b64 {%0, %1}, %2;" : "=f"(S2[2 * i]), "=f"(S2[2 * i + 1]) : "l"(s2p[i]));
    }

    // ---- epilogue: y[n,d] = sum_s h_final * C_last ----
    const float wd = w_in[d];
    const float bd = b_in[d];
    const float xlast = xr[N_BANDS - 1];
    float y = 0.f;
    #pragma unroll
    for (int s = 0; s < DS; ++s) {
        float av = a[s];
        // geometric: S0 = sum_{j=0}^{223} a^j  (exact closed form, no truncation)
        float S0 = (1.0f - __powf(av, (float)N_BANDS)) / (1.0f - av);
        float wbv = sh_wb[s], bbv = sh_bb[s];
        float hf = wd * wbv * S2[s] + (wd * bbv + bd * wbv) * S1[s] + bd * bbv * S0;
        float cl = xlast * sh_wc[s] + sh_bc[s];
        y += hf * cl;
    }
    float o = y + Dvec[d] * (xlast * wd + bd);
    sh_out[nl][d] = o;
    __syncthreads();

    // ---- z = out @ Wo^T + bo ----
    float z = bo[d];
    #pragma unroll 16
    for (int k = 0; k < DM; ++k)
        z += sh_out[nl][k] * sh_WoT[k][d];
    sh_z[nl][d] = z;
    __syncthreads();

    // ---- layernorm over d (single pass: sum + sumsq) ----
    float sum = 0.f, sumsq = 0.f;
    #pragma unroll 16
    for (int k = 0; k < DM; ++k) {
        float v = sh_z[nl][k];
        sum += v;
        sumsq += v * v;
    }
    float mu  = sum * (1.0f / DM);
    float var = sumsq * (1.0f / DM) - mu * mu;
    float r = rsqrtf(var + LN_EPS);

    out[(size_t)(n0 + nl) * DM + d] = gamma[d] * (z - mu) * r + beta[d];
}

extern "C" void kernel_launch(void* const* d_in, const int* in_sizes, int n_in,
                              void* d_out, int out_size) {
    const float* x     = (const float*)d_in[0];
    const float* w_in  = (const float*)d_in[1];
    const float* b_in  = (const float*)d_in[2];
    const float* A_log = (const float*)d_in[3];
    const float* Wb    = (const float*)d_in[4];
    const float* Wc    = (const float*)d_in[5];
    const float* Dv    = (const float*)d_in[6];
    const float* Wo    = (const float*)d_in[7];
    const float* bo    = (const float*)d_in[8];
    const float* gm    = (const float*)d_in[9];
    const float* bt    = (const float*)d_in[10];
    float* out = (float*)d_out;

    int N = in_sizes[0] / N_BANDS;          // 4096
    int grid = N / N_TILE;                  // 1024 blocks
    spectral_ssm_kernel<<<grid, NTHREADS>>>(x, w_in, b_in, A_log, Wb, Wc, Dv,
                                            Wo, bo, gm, bt, out);
}